// round 11
// baseline (speedup 1.0000x reference)
#include <cuda_runtime.h>
#include <cuda_fp16.h>
#include <cstdint>
#include <cstdio>

// ---------------- problem constants ----------------
#define BB_ 2
#define TT_ 2048
#define CC_ 1024
#define HH_ 16
#define DD_ 64

// exp(s/8) = 2^(s * log2(e)/8); folded into Q at the QKV epilogue
#define SOFTMAX_SCL 0.18033688011112042f

// ---------------- scratch: fp16 stored as unsigned (half2 units) ----------------
__device__ __align__(16) unsigned g_Xt[BB_*TT_*CC_/2];      // X fp16 [m][k]
__device__ __align__(16) unsigned g_Wt[4*CC_*CC_/2];        // Wq|Wk|Wv|Wo fp16 [n][k]
__device__ __align__(16) unsigned g_Q [BB_*HH_*TT_*DD_/2];  // [b,h,t,d]  (pre-scaled)
__device__ __align__(16) unsigned g_K [BB_*HH_*TT_*DD_/2];  // [b,h,t,d]
__device__ __align__(16) unsigned g_V [BB_*HH_*TT_*DD_/2];  // [b,h,t,d]
__device__ __align__(16) unsigned g_Yc[BB_*TT_*CC_/2];      // merged heads [b,t,c]

// ---------------- helpers ----------------
__device__ __forceinline__ float ex2(float x) {
    float y;
    asm("ex2.approx.f32 %0, %1;" : "=f"(y) : "f"(x));
    return y;
}
__device__ __forceinline__ unsigned ex2h2(unsigned x) {
    unsigned y;
    asm("ex2.approx.f16x2 %0, %1;" : "=r"(y) : "r"(x));
    return y;
}
__device__ __forceinline__ unsigned hsub2(unsigned a, unsigned b) {
    unsigned y;
    asm("sub.f16x2 %0, %1, %2;" : "=r"(y) : "r"(a), "r"(b));
    return y;
}
__device__ __forceinline__ unsigned packh2(float a, float b) {
    __half2 h = __floats2half2_rn(a, b);
    return *(unsigned*)&h;
}
__device__ __forceinline__ void mma16(float* d, const unsigned* a, const unsigned* b) {
    asm volatile(
        "mma.sync.aligned.m16n8k16.row.col.f32.f16.f16.f32 "
        "{%0,%1,%2,%3},{%4,%5,%6,%7},{%8,%9},{%0,%1,%2,%3};"
        : "+f"(d[0]), "+f"(d[1]), "+f"(d[2]), "+f"(d[3])
        : "r"(a[0]), "r"(a[1]), "r"(a[2]), "r"(a[3]),
          "r"(b[0]), "r"(b[1]));
}
__device__ __forceinline__ void ldsm4(unsigned* r, unsigned addr) {
    asm volatile("ldmatrix.sync.aligned.m8n8.x4.shared.b16 {%0,%1,%2,%3}, [%4];"
        : "=r"(r[0]), "=r"(r[1]), "=r"(r[2]), "=r"(r[3]) : "r"(addr));
}
__device__ __forceinline__ void ldsm4t(unsigned* r, unsigned addr) {
    asm volatile("ldmatrix.sync.aligned.m8n8.x4.trans.shared.b16 {%0,%1,%2,%3}, [%4];"
        : "=r"(r[0]), "=r"(r[1]), "=r"(r[2]), "=r"(r[3]) : "r"(addr));
}
// 1D bulk async copy: one instruction per 128B row, mbarrier-completed
__device__ __forceinline__ void bulkcp(unsigned dst, const void* src,
                                       unsigned bytes, unsigned mbar) {
    asm volatile(
        "cp.async.bulk.shared::cta.global.mbarrier::complete_tx::bytes "
        "[%0], [%1], %2, [%3];"
        :: "r"(dst), "l"(src), "r"(bytes), "r"(mbar) : "memory");
}
#define MBAR_INIT(addr, cnt) \
    asm volatile("mbarrier.init.shared.b64 [%0], %1;" \
        :: "r"(addr), "r"((unsigned)(cnt)) : "memory")
#define MBAR_EXPECT(addr, bytes) \
    asm volatile("mbarrier.arrive.expect_tx.shared.b64 _, [%0], %1;" \
        :: "r"(addr), "r"((unsigned)(bytes)) : "memory")
__device__ __forceinline__ void mbar_wait(unsigned addr, unsigned parity) {
    asm volatile(
        "{\n\t.reg .pred P;\n\t"
        "W_%=:\n\t"
        "mbarrier.try_wait.parity.acquire.cta.shared::cta.b64 P, [%0], %1, 0x989680;\n\t"
        "@P bra D_%=;\n\t"
        "bra W_%=;\n\t"
        "D_%=:\n\t}"
        :: "r"(addr), "r"(parity) : "memory");
}
#define FENCE_ASYNC() asm volatile("fence.proxy.async.shared::cta;" ::: "memory")
__device__ __forceinline__ unsigned smem_u32(const void* p) {
    return (unsigned)__cvta_generic_to_shared(p);
}

// ============================================================================
// one-shot fp16 conversion: X (1M float4) + 4 weights (256K float4 each)
// ============================================================================
__global__ void __launch_bounds__(256) conv_kernel(
    const float4* __restrict__ X,  const float4* __restrict__ Wq,
    const float4* __restrict__ Wk, const float4* __restrict__ Wv,
    const float4* __restrict__ Wo)
{
    int i = blockIdx.x * 256 + threadIdx.x;          // 0 .. 2M-1
    const float4* src;
    uint2* dst;
    if (i < (1 << 20)) {
        src = X + i;
        dst = (uint2*)g_Xt + i;
    } else {
        int j = i - (1 << 20);
        int w = j >> 18, r = j & 0x3FFFF;
        const float4* s4 = (w == 0) ? Wq : (w == 1) ? Wk : (w == 2) ? Wv : Wo;
        src = s4 + r;
        dst = (uint2*)g_Wt + (w << 18) + r;
    }
    float4 v = *src;
    *dst = make_uint2(packh2(v.x, v.y), packh2(v.z, v.w));
}

// ============================================================================
// fp16 GEMM: C[m,n] = sum_k A[m,k]*B[n,k]  (NT), K=1024.
// CTA 128x128, 4 warps (2m x 2n), warp tile 64x64, m16n8k16 + ldmatrix.x4.
// Loads: cp.async.bulk (128B/row, 256 instr/chunk vs 2048 LDGSTS) into a
// 3-stage ring, completion via per-stage mbarrier expect_tx.
// 128 thr; 110.7KB smem -> 2 CTAs/SM.
// MODE 1: epilogue -> g_Q (pre-scaled) / g_K / g_V (all [b,h,t,d], coalesced).
// MODE 0: A=g_Yc, writes fp32 Cout.
// ============================================================================
#define G_ROW_B 144u
#define G_A_B   18432u          // A block bytes (128*144)
#define G_STG_B 36864u          // A+B per stage
#define GEMM_SMEM_BYTES (128 + 3*36864)

template<int MODE>
__global__ void __launch_bounds__(128, 2) gemm_fp16(
    const __half* __restrict__ A,
    const __half* __restrict__ B,
    float* __restrict__ Cout)
{
    extern __shared__ unsigned smem[];
    const unsigned sbase = smem_u32(smem);          // mbar[3] @ +0, stages @ +128

    const int tid  = threadIdx.x;
    const int bm   = blockIdx.y * 128;
    const int bn   = blockIdx.x * 128;
    const int warp = tid >> 5, lane = tid & 31;
    const int g = lane >> 2, t = lane & 3;
    const int wm = (warp & 1) * 64;          // warp m offset
    const int wn = (warp >> 1) * 64;         // warp n offset

    const __half* Ap = A + (size_t)bm * 1024;
    const __half* Bp = B + (size_t)bn * 1024;

    if (tid == 0) {
        MBAR_INIT(sbase,      1);
        MBAR_INIT(sbase + 8,  1);
        MBAR_INIT(sbase + 16, 1);
        FENCE_ASYNC();
    }
    __syncthreads();

    float acc[4][8][4];
    #pragma unroll
    for (int i = 0; i < 4; i++)
        #pragma unroll
        for (int j = 0; j < 8; j++)
            #pragma unroll
            for (int r = 0; r < 4; r++) acc[i][j][r] = 0.f;

    // ldmatrix per-lane byte offsets relative to stage base
    unsigned aRel[4], bRel[4];
    {
        int rA = (lane & 15), kA = (lane >> 4) * 8;
        #pragma unroll
        for (int im = 0; im < 4; im++)
            aRel[im] = (unsigned)((wm + im * 16 + rA) * 72 + kA) * 2u;
        int rB = ((lane >> 4) & 1) * 8 + (lane & 7);
        int kB = ((lane >> 3) & 1) * 8;
        #pragma unroll
        for (int j = 0; j < 4; j++)
            bRel[j] = G_A_B + (unsigned)((wn + j * 16 + rB) * 72 + kB) * 2u;
    }

    // one A row + one B row (128B each) per thread per stage
    auto issue_stage = [&](int s, int k0) {
        const unsigned mb = sbase + 8u * (unsigned)s;
        const unsigned st = sbase + 128u + (unsigned)s * G_STG_B;
        if (tid == 0) MBAR_EXPECT(mb, 32768u);
        bulkcp(st + (unsigned)tid * G_ROW_B,
               Ap + (size_t)tid * 1024 + k0, 128u, mb);
        bulkcp(st + G_A_B + (unsigned)tid * G_ROW_B,
               Bp + (size_t)tid * 1024 + k0, 128u, mb);
    };

    issue_stage(0, 0);
    issue_stage(1, 64);

    #pragma unroll 1
    for (int i = 0; i < 16; ++i) {
        const int s = i % 3;
        mbar_wait(sbase + 8u * (unsigned)s, (unsigned)((i / 3) & 1));
        __syncthreads();                       // all done reading buffer (i-1)%3
        if (i + 2 < 16)
            issue_stage((i + 2) % 3, (i + 2) * 64);

        const unsigned stg = sbase + 128u + (unsigned)s * G_STG_B;
        #pragma unroll
        for (int ks8 = 0; ks8 < 4; ks8++) {                 // 4 k-steps of 16
            const unsigned ko = (unsigned)ks8 * 32u;        // 16 halves = 32B
            unsigned afr[4][4], bfr[8][2];
            #pragma unroll
            for (int im = 0; im < 4; im++)
                ldsm4(afr[im], stg + aRel[im] + ko);
            #pragma unroll
            for (int j = 0; j < 4; j++)
                ldsm4(&bfr[2*j][0], stg + bRel[j] + ko);
            #pragma unroll
            for (int im = 0; im < 4; im++)
                #pragma unroll
                for (int in = 0; in < 8; in++)
                    mma16(acc[im][in], afr[im], bfr[in]);
        }
    }

    // ---------------- epilogue ----------------
    if (MODE == 0) {
        #pragma unroll
        for (int im = 0; im < 4; im++) {
            #pragma unroll
            for (int in = 0; in < 8; in++) {
                int r0 = bm + wm + im * 16 + g;
                int c0 = bn + wn + in * 8 + 2 * t;
                *(float2*)(Cout + (size_t)r0 * 1024 + c0) =
                    make_float2(acc[im][in][0], acc[im][in][1]);
                *(float2*)(Cout + (size_t)(r0 + 8) * 1024 + c0) =
                    make_float2(acc[im][in][2], acc[im][in][3]);
            }
        }
    } else {
        const int which = bn >> 10;
        const int nloc  = bn & 1023;
        const float qs = (which == 0) ? SOFTMAX_SCL : 1.f;  // fold softmax scale into Q
        unsigned* dst = (which == 0) ? g_Q : (which == 1) ? g_K : g_V;
        #pragma unroll
        for (int im = 0; im < 4; im++) {
            #pragma unroll
            for (int in = 0; in < 8; in++) {
                int r0 = bm + wm + im * 16 + g;      // m = b*2048 + t
                int b  = r0 >> 11, tt = r0 & 2047;
                int n0 = nloc + wn + in * 8 + 2 * t;
                int h  = n0 >> 6, d = n0 & 63;
                size_t base = ((size_t)(b * HH_ + h) * TT_ + tt) * (DD_/2) + (d >> 1);
                dst[base] = packh2(acc[im][in][0] * qs, acc[im][in][1] * qs);
                dst[base + 8 * (DD_/2)] = packh2(acc[im][in][2] * qs, acc[im][in][3] * qs);
            }
        }
    }
}

// ============================================================================
// Flash attention (causal), register-resident P, f16x2 softmax,
// row sums via ones-column mma, V via ldmatrix.x4.trans.
// K/V 64-row tiles via cp.async.bulk (128 instr/tile vs 1024 LDGSTS) into a
// 3-stage mbarrier ring; Q folded into stage-0's expect_tx.
// CTA = 128 q-rows, 4 warps x 32 q-rows, 128 thr; 73.9KB smem -> 2 CTAs/SM.
// ============================================================================
// layout: mbar[3] @ +0, Q[128][72h] @ +128 (18432B), stages @ +18560,
//         each stage: K 64x144 (9216B) then V 64x144 (9216B)
#define A_Q_OFF  128u
#define A_KV0    18560u
#define A_STG_B  18432u
#define A_V_OFF  9216u
#define ATTN_SMEM_BYTES (128 + 18432 + 3*18432)

__global__ void __launch_bounds__(128, 2) attn_kernel()
{
    extern __shared__ unsigned smem[];
    const unsigned sbase = smem_u32(smem);

    const int bh = blockIdx.y;                    // b*16 + h
    const int qt = gridDim.x - 1 - blockIdx.x;    // biggest tiles first
    const int q0 = qt * 128;
    const int nkt = (q0 >> 6) + 2;                // k-tiles: kt = 0 .. q0+64  (>=2)

    const __half* Qp = (const __half*)g_Q + (size_t)bh * TT_ * DD_;
    const __half* Kp = (const __half*)g_K + (size_t)bh * TT_ * DD_;
    const __half* Vp = (const __half*)g_V + (size_t)bh * TT_ * DD_;

    const int tid = threadIdx.x;
    const int warp = tid >> 5, lane = tid & 31;
    const int g = lane >> 2, t = lane & 3;

    if (tid == 0) {
        MBAR_INIT(sbase,      1);
        MBAR_INIT(sbase + 8,  1);
        MBAR_INIT(sbase + 16, 1);
        FENCE_ASYNC();
    }
    __syncthreads();

    // ldmatrix per-lane offsets (qRel absolute from sbase; k/v relative to stage)
    unsigned qRel[2], kRel[4], vRel[4];
    {
        int rA = (lane & 15), kA = (lane >> 4) * 8;
        #pragma unroll
        for (int im = 0; im < 2; im++)
            qRel[im] = A_Q_OFF + (unsigned)((warp * 32 + im * 16 + rA) * 72 + kA) * 2u;
        int rB = ((lane >> 4) & 1) * 8 + (lane & 7);
        int kB = ((lane >> 3) & 1) * 8;
        #pragma unroll
        for (int j = 0; j < 4; j++)
            kRel[j] = (unsigned)((j * 16 + rB) * 72 + kB) * 2u;
        int rV = lane & 15, cV = (lane >> 4) * 8;
        #pragma unroll
        for (int j = 0; j < 4; j++)
            vRel[j] = A_V_OFF + (unsigned)(rV * 72 + j * 16 + cV) * 2u;
    }

    // one 128B row per thread: tid<64 -> K row tid, tid>=64 -> V row tid-64
    auto issue_kv = [&](int s, int kt, unsigned expect_bytes) {
        const unsigned mb = sbase + 8u * (unsigned)s;
        const unsigned st = A_KV0 + sbase + (unsigned)s * A_STG_B;
        if (tid == 0) MBAR_EXPECT(mb, expect_bytes);
        const int r = tid & 63;
        if (tid < 64)
            bulkcp(st + (unsigned)r * 144u, Kp + (size_t)(kt + r) * DD_, 128u, mb);
        else
            bulkcp(st + A_V_OFF + (unsigned)r * 144u, Vp + (size_t)(kt + r) * DD_, 128u, mb);
    };

    // prologue: stage0 expects Q (16KB) + KV (16KB); Q rides mbar0
    issue_kv(0, 0, 32768u);
    bulkcp(sbase + A_Q_OFF + (unsigned)tid * 144u,
           Qp + (size_t)(q0 + tid) * DD_, 128u, sbase);
    issue_kv(1, 64, 16384u);

    float m[2][2];
    #pragma unroll
    for (int i = 0; i < 2; i++)
        #pragma unroll
        for (int j = 0; j < 2; j++) m[i][j] = -INFINITY;

    // o[im][0..7] = output, o[im][8] = row sums (V ones column)
    float o[2][9][4];
    #pragma unroll
    for (int im = 0; im < 2; im++)
        #pragma unroll
        for (int in = 0; in < 9; in++)
            #pragma unroll
            for (int r = 0; r < 4; r++) o[im][in][r] = 0.f;

    const unsigned ones_b[2] = {0x3C003C00u, 0x3C003C00u};  // half2(1,1)
    const int wrow_min = q0 + warp * 32;

    #pragma unroll 1
    for (int it = 0; it < nkt; ++it) {
        const int kt = it * 64;
        const int s = it % 3;
        mbar_wait(sbase + 8u * (unsigned)s, (unsigned)((it / 3) & 1));
        __syncthreads();
        if (it + 2 < nkt)
            issue_kv((it + 2) % 3, kt + 128, 16384u);

        if (kt < wrow_min + 32) {
            const unsigned stg = A_KV0 + sbase + (unsigned)s * A_STG_B;

            // ---- S = Q K^T (pre-scaled, log2 domain) ----
            float sreg[2][8][4];
            #pragma unroll
            for (int im = 0; im < 2; im++)
                #pragma unroll
                for (int in = 0; in < 8; in++)
                    #pragma unroll
                    for (int r = 0; r < 4; r++) sreg[im][in][r] = 0.f;

            #pragma unroll
            for (int ks8 = 0; ks8 < 4; ks8++) {
                const unsigned ko = (unsigned)ks8 * 32u;
                unsigned qa[2][4], kb[8][2];
                #pragma unroll
                for (int im = 0; im < 2; im++)
                    ldsm4(qa[im], sbase + qRel[im] + ko);
                #pragma unroll
                for (int j = 0; j < 4; j++)
                    ldsm4(&kb[2*j][0], stg + kRel[j] + ko);
                #pragma unroll
                for (int im = 0; im < 2; im++)
                    #pragma unroll
                    for (int in = 0; in < 8; in++)
                        mma16(sreg[im][in], qa[im], kb[in]);
            }

            // ---- causal mask + row max (fp32) ----
            const bool needmask = (kt + 63 > wrow_min);
            float mx[2][2];
            #pragma unroll
            for (int im = 0; im < 2; im++) {
                const int rqa = wrow_min + im * 16 + g;
                const int rqb = rqa + 8;
                float a0 = -INFINITY, a1 = -INFINITY;
                #pragma unroll
                for (int in = 0; in < 8; in++) {
                    int c = kt + in * 8 + 2 * t;
                    float x0 = sreg[im][in][0];
                    float x1 = sreg[im][in][1];
                    float x2 = sreg[im][in][2];
                    float x3 = sreg[im][in][3];
                    if (needmask) {
                        if (c     > rqa) x0 = -INFINITY;
                        if (c + 1 > rqa) x1 = -INFINITY;
                        if (c     > rqb) x2 = -INFINITY;
                        if (c + 1 > rqb) x3 = -INFINITY;
                    }
                    sreg[im][in][0] = x0; sreg[im][in][1] = x1;
                    sreg[im][in][2] = x2; sreg[im][in][3] = x3;
                    a0 = fmaxf(a0, fmaxf(x0, x1));
                    a1 = fmaxf(a1, fmaxf(x2, x3));
                }
                a0 = fmaxf(a0, __shfl_xor_sync(0xffffffffu, a0, 1));
                a0 = fmaxf(a0, __shfl_xor_sync(0xffffffffu, a0, 2));
                a1 = fmaxf(a1, __shfl_xor_sync(0xffffffffu, a1, 1));
                a1 = fmaxf(a1, __shfl_xor_sync(0xffffffffu, a1, 2));
                mx[im][0] = a0; mx[im][1] = a1;
            }

            float cor[2][2];
            #pragma unroll
            for (int im = 0; im < 2; im++)
                #pragma unroll
                for (int hf = 0; hf < 2; hf++) {
                    float nm = fmaxf(m[im][hf], mx[im][hf]);
                    cor[im][hf] = ex2(m[im][hf] - nm);
                    m[im][hf] = nm;
                }

            // ---- P = 2^(x-m) via f16x2 MUFU; pk is PV-A-fragment-ready ----
            unsigned pk[2][8][2];
            #pragma unroll
            for (int im = 0; im < 2; im++) {
                const unsigned mh0 = packh2(m[im][0], m[im][0]);
                const unsigned mh1 = packh2(m[im][1], m[im][1]);
                #pragma unroll
                for (int in = 0; in < 8; in++) {
                    unsigned xa = packh2(sreg[im][in][0], sreg[im][in][1]);
                    unsigned xb = packh2(sreg[im][in][2], sreg[im][in][3]);
                    pk[im][in][0] = ex2h2(hsub2(xa, mh0));
                    pk[im][in][1] = ex2h2(hsub2(xb, mh1));
                }
            }

            // rescale O (incl. sum column 8)
            #pragma unroll
            for (int im = 0; im < 2; im++)
                #pragma unroll
                for (int in = 0; in < 9; in++) {
                    o[im][in][0] *= cor[im][0]; o[im][in][1] *= cor[im][0];
                    o[im][in][2] *= cor[im][1]; o[im][in][3] *= cor[im][1];
                }

            // ---- O += P V  (+ row sums via ones column) ----
            #pragma unroll
            for (int j2 = 0; j2 < 4; j2++) {              // kv k-steps of 16
                const unsigned kvo = (unsigned)j2 * 2304u;  // 16 kv-rows * 144B
                unsigned vb[8][2];
                #pragma unroll
                for (int j = 0; j < 4; j++)
                    ldsm4t(&vb[2*j][0], stg + vRel[j] + kvo);
                #pragma unroll
                for (int im = 0; im < 2; im++) {
                    unsigned a[4];
                    a[0] = pk[im][2*j2  ][0];
                    a[1] = pk[im][2*j2  ][1];
                    a[2] = pk[im][2*j2+1][0];
                    a[3] = pk[im][2*j2+1][1];
                    #pragma unroll
                    for (int in = 0; in < 8; in++)
                        mma16(o[im][in], a, vb[in]);
                    mma16(o[im][8], a, ones_b);           // row sums
                }
            }
        }
    }

    // ---- normalize by l = o[im][8], write half2 merged-head output ----
    const int b = bh >> 4, h = bh & 15;
    #pragma unroll
    for (int im = 0; im < 2; im++) {
        float inv0 = 1.f / o[im][8][0];
        float inv1 = 1.f / o[im][8][2];
        int r0 = q0 + warp * 32 + im * 16 + g;
        #pragma unroll
        for (int in = 0; in < 8; in++) {
            int cu = h * 32 + in * 4 + t;             // half2 unit col
            size_t base0 = ((size_t)(b * TT_ + r0)     * (CC_/2)) + cu;
            size_t base1 = ((size_t)(b * TT_ + r0 + 8) * (CC_/2)) + cu;
            g_Yc[base0] = packh2(o[im][in][0] * inv0, o[im][in][1] * inv0);
            g_Yc[base1] = packh2(o[im][in][2] * inv1, o[im][in][3] * inv1);
        }
    }
}

// ============================================================================
// launch
// ============================================================================
extern "C" void kernel_launch(void* const* d_in, const int* in_sizes, int n_in,
                              void* d_out, int out_size)
{
    const float* X  = (const float*)d_in[0];
    const float* Wq = (const float*)d_in[1];
    const float* Wk = (const float*)d_in[2];
    const float* Wv = (const float*)d_in[3];
    const float* Wo = (const float*)d_in[4];
    float* out = (float*)d_out;

    cudaFuncSetAttribute(gemm_fp16<1>, cudaFuncAttributeMaxDynamicSharedMemorySize,
                         GEMM_SMEM_BYTES);
    cudaFuncSetAttribute(gemm_fp16<0>, cudaFuncAttributeMaxDynamicSharedMemorySize,
                         GEMM_SMEM_BYTES);
    cudaFuncSetAttribute(attn_kernel, cudaFuncAttributeMaxDynamicSharedMemorySize,
                         ATTN_SMEM_BYTES);

    unsigned *Xt = nullptr, *Wt = nullptr, *Yc = nullptr;
    cudaGetSymbolAddress((void**)&Xt, g_Xt);
    cudaGetSymbolAddress((void**)&Wt, g_Wt);
    cudaGetSymbolAddress((void**)&Yc, g_Yc);

    // 0) fp16 pre-conversion
    conv_kernel<<<8192, 256>>>((const float4*)X, (const float4*)Wq,
                               (const float4*)Wk, (const float4*)Wv,
                               (const float4*)Wo);

    // 1) QKV: M=4096, N=3072 (24 tiles of 128), K=1024
    gemm_fp16<1><<<dim3(24, 32), 128, GEMM_SMEM_BYTES>>>(
        (const __half*)Xt, (const __half*)Wt, nullptr);

    // 2) attention: grid = (q-tiles=16, b*h=32)
    attn_kernel<<<dim3(16, 32), 128, ATTN_SMEM_BYTES>>>();

    // 3) output projection: M=4096, N=1024 (8 tiles of 128), K=1024
    gemm_fp16<0><<<dim3(8, 32), 128, GEMM_SMEM_BYTES>>>(
        (const __half*)Yc, (const __half*)Wt + 3*1024*1024, out);
}

// round 13
// speedup vs baseline: 1.6036x; 1.6036x over previous
#include <cuda_runtime.h>
#include <cuda_fp16.h>
#include <cstdint>
#include <cstdio>

// ---------------- problem constants ----------------
#define BB_ 2
#define TT_ 2048
#define CC_ 1024
#define HH_ 16
#define DD_ 64

// exp(s/8) = 2^(s * log2(e)/8); folded into Q at the QKV epilogue
#define SOFTMAX_SCL 0.18033688011112042f

// ---------------- scratch: fp16 stored as unsigned (half2 units) ----------------
__device__ __align__(16) unsigned g_Xt[BB_*TT_*CC_/2];      // X fp16 [m][k]
__device__ __align__(16) unsigned g_Wt[4*CC_*CC_/2];        // Wq|Wk|Wv|Wo fp16 [n][k]
__device__ __align__(16) unsigned g_Q [BB_*HH_*TT_*DD_/2];  // [b,h,t,d]  (pre-scaled)
__device__ __align__(16) unsigned g_K [BB_*HH_*TT_*DD_/2];  // [b,h,t,d]
__device__ __align__(16) unsigned g_V [BB_*HH_*TT_*DD_/2];  // [b,h,t,d]
__device__ __align__(16) unsigned g_Yc[BB_*TT_*CC_/2];      // merged heads [b,t,c]

// ---------------- helpers ----------------
__device__ __forceinline__ float ex2(float x) {
    float y;
    asm("ex2.approx.f32 %0, %1;" : "=f"(y) : "f"(x));
    return y;
}
__device__ __forceinline__ unsigned ex2h2(unsigned x) {
    unsigned y;
    asm("ex2.approx.f16x2 %0, %1;" : "=r"(y) : "r"(x));
    return y;
}
__device__ __forceinline__ unsigned hsub2(unsigned a, unsigned b) {
    unsigned y;
    asm("sub.f16x2 %0, %1, %2;" : "=r"(y) : "r"(a), "r"(b));
    return y;
}
__device__ __forceinline__ unsigned packh2(float a, float b) {
    __half2 h = __floats2half2_rn(a, b);
    return *(unsigned*)&h;
}
__device__ __forceinline__ void mma16(float* d, const unsigned* a, const unsigned* b) {
    asm volatile(
        "mma.sync.aligned.m16n8k16.row.col.f32.f16.f16.f32 "
        "{%0,%1,%2,%3},{%4,%5,%6,%7},{%8,%9},{%0,%1,%2,%3};"
        : "+f"(d[0]), "+f"(d[1]), "+f"(d[2]), "+f"(d[3])
        : "r"(a[0]), "r"(a[1]), "r"(a[2]), "r"(a[3]),
          "r"(b[0]), "r"(b[1]));
}
__device__ __forceinline__ void ldsm4(unsigned* r, unsigned addr) {
    asm volatile("ldmatrix.sync.aligned.m8n8.x4.shared.b16 {%0,%1,%2,%3}, [%4];"
        : "=r"(r[0]), "=r"(r[1]), "=r"(r[2]), "=r"(r[3]) : "r"(addr));
}
__device__ __forceinline__ void ldsm4t(unsigned* r, unsigned addr) {
    asm volatile("ldmatrix.sync.aligned.m8n8.x4.trans.shared.b16 {%0,%1,%2,%3}, [%4];"
        : "=r"(r[0]), "=r"(r[1]), "=r"(r[2]), "=r"(r[3]) : "r"(addr));
}
__device__ __forceinline__ void cpa(unsigned dst, const void* src) {
    asm volatile("cp.async.cg.shared.global [%0], [%1], 16;" :: "r"(dst), "l"(src));
}
#define CP_COMMIT() asm volatile("cp.async.commit_group;")
#define CP_WAIT1()  asm volatile("cp.async.wait_group 1;")
#define CP_WAIT0()  asm volatile("cp.async.wait_group 0;")
__device__ __forceinline__ unsigned smem_u32(const void* p) {
    return (unsigned)__cvta_generic_to_shared(p);
}

// ============================================================================
// one-shot fp16 conversion: X (1M float4) + 4 weights (256K float4 each)
// ============================================================================
__global__ void __launch_bounds__(256) conv_kernel(
    const float4* __restrict__ X,  const float4* __restrict__ Wq,
    const float4* __restrict__ Wk, const float4* __restrict__ Wv,
    const float4* __restrict__ Wo)
{
    int i = blockIdx.x * 256 + threadIdx.x;          // 0 .. 2M-1
    const float4* src;
    uint2* dst;
    if (i < (1 << 20)) {
        src = X + i;
        dst = (uint2*)g_Xt + i;
    } else {
        int j = i - (1 << 20);
        int w = j >> 18, r = j & 0x3FFFF;
        const float4* s4 = (w == 0) ? Wq : (w == 1) ? Wk : (w == 2) ? Wv : Wo;
        src = s4 + r;
        dst = (uint2*)g_Wt + (w << 18) + r;
    }
    float4 v = *src;
    *dst = make_uint2(packh2(v.x, v.y), packh2(v.z, v.w));
}

// ============================================================================
// fp16 GEMM: C[m,n] = sum_k A[m,k]*B[n,k]  (NT), K=1024.
// CTA 128x128, 4 warps (2m x 2n), warp tile 64x64, m16n8k16 + ldmatrix.x4.
// 3-stage cp.async ring (wait_group 1), single __syncthreads per k-chunk.
// 128 thr; 110.6KB smem -> 2 CTAs/SM.
// MODE 1: grid (8,32) = ONE uniform wave; each CTA runs 3 passes over
//         Wq/Wk/Wv at the same (bm,bn), scattering to g_Q/g_K/g_V.
// MODE 0: single pass, A=g_Yc, writes fp32 Cout (grid (8,32), one wave).
// ============================================================================
#define G_ROW_B 144u
#define G_A_B   18432u          // A block bytes (128*144)
#define G_STG_B 36864u          // A+B per stage
#define GEMM_SMEM_BYTES (3*36864)

template<int MODE>
__global__ void __launch_bounds__(128, 2) gemm_fp16(
    const __half* __restrict__ A,
    const __half* __restrict__ B,
    float* __restrict__ Cout)
{
    extern __shared__ unsigned smem[];
    const unsigned sbase = smem_u32(smem);

    const int tid  = threadIdx.x;
    const int bm   = blockIdx.y * 128;
    const int bn   = blockIdx.x * 128;        // 0..896 (N region = 1024)
    const int warp = tid >> 5, lane = tid & 31;
    const int g = lane >> 2, t = lane & 3;
    const int wm = (warp & 1) * 64;           // warp m offset
    const int wn = (warp >> 1) * 64;          // warp n offset

    const __half* Ap = A + (size_t)bm * 1024;

    // ldmatrix per-lane relative byte offsets
    unsigned aRel[4], bRel[4];
    {
        int rA = (lane & 15), kA = (lane >> 4) * 8;
        #pragma unroll
        for (int im = 0; im < 4; im++)
            aRel[im] = (unsigned)((wm + im * 16 + rA) * 72 + kA) * 2u;
        int rB = ((lane >> 4) & 1) * 8 + (lane & 7);
        int kB = ((lane >> 3) & 1) * 8;
        #pragma unroll
        for (int j = 0; j < 4; j++)
            bRel[j] = G_A_B + (unsigned)((wn + j * 16 + rB) * 72 + kB) * 2u;
    }

    const int NPASS = (MODE == 1) ? 3 : 1;
    #pragma unroll 1
    for (int pass = 0; pass < NPASS; ++pass) {
        if (pass) __syncthreads();            // smem reuse across passes

        const __half* Bp = B + ((size_t)pass << 20) + (size_t)bn * 1024;

        float acc[4][8][4];
        #pragma unroll
        for (int i = 0; i < 4; i++)
            #pragma unroll
            for (int j = 0; j < 8; j++)
                #pragma unroll
                for (int r = 0; r < 4; r++) acc[i][j][r] = 0.f;

        auto load_stage = [&](int s, int k0) {
            const unsigned st = sbase + (unsigned)s * G_STG_B;
            #pragma unroll
            for (int i = 0; i < 8; i++) {                   // A: 1024 chunks
                int id = tid + (i << 7);
                int r = id >> 3, c = id & 7;
                cpa(st + (unsigned)r * G_ROW_B + (unsigned)c * 16u,
                    Ap + (size_t)r * 1024 + k0 + c * 8);
            }
            #pragma unroll
            for (int i = 0; i < 8; i++) {                   // B: 1024 chunks
                int id = tid + (i << 7);
                int r = id >> 3, c = id & 7;
                cpa(st + G_A_B + (unsigned)r * G_ROW_B + (unsigned)c * 16u,
                    Bp + (size_t)r * 1024 + k0 + c * 8);
            }
        };

        load_stage(0, 0);
        CP_COMMIT();
        load_stage(1, 64);
        CP_COMMIT();

        int s = 0;
        #pragma unroll 1
        for (int i = 0; i < 16; ++i) {
            if (i + 1 < 16) { CP_WAIT1(); } else { CP_WAIT0(); }
            __syncthreads();
            if (i + 2 < 16) {
                int s2 = s + 2; if (s2 >= 3) s2 -= 3;
                load_stage(s2, (i + 2) * 64);
                CP_COMMIT();
            }

            const unsigned stg = sbase + (unsigned)s * G_STG_B;
            #pragma unroll
            for (int ks8 = 0; ks8 < 4; ks8++) {             // 4 k-steps of 16
                const unsigned ko = (unsigned)ks8 * 32u;    // 16 halves = 32B
                unsigned afr[4][4], bfr[8][2];
                #pragma unroll
                for (int im = 0; im < 4; im++)
                    ldsm4(afr[im], stg + aRel[im] + ko);
                #pragma unroll
                for (int j = 0; j < 4; j++)
                    ldsm4(&bfr[2*j][0], stg + bRel[j] + ko);
                #pragma unroll
                for (int im = 0; im < 4; im++)
                    #pragma unroll
                    for (int in = 0; in < 8; in++)
                        mma16(acc[im][in], afr[im], bfr[in]);
            }
            if (++s >= 3) s = 0;
        }

        // ---------------- epilogue ----------------
        if (MODE == 0) {
            #pragma unroll
            for (int im = 0; im < 4; im++) {
                #pragma unroll
                for (int in = 0; in < 8; in++) {
                    int r0 = bm + wm + im * 16 + g;
                    int c0 = bn + wn + in * 8 + 2 * t;
                    *(float2*)(Cout + (size_t)r0 * 1024 + c0) =
                        make_float2(acc[im][in][0], acc[im][in][1]);
                    *(float2*)(Cout + (size_t)(r0 + 8) * 1024 + c0) =
                        make_float2(acc[im][in][2], acc[im][in][3]);
                }
            }
        } else {
            const float qs = (pass == 0) ? SOFTMAX_SCL : 1.f;
            unsigned* dst = (pass == 0) ? g_Q : (pass == 1) ? g_K : g_V;
            #pragma unroll
            for (int im = 0; im < 4; im++) {
                #pragma unroll
                for (int in = 0; in < 8; in++) {
                    int r0 = bm + wm + im * 16 + g;      // m = b*2048 + t
                    int b  = r0 >> 11, tt = r0 & 2047;
                    int n0 = bn + wn + in * 8 + 2 * t;
                    int h  = n0 >> 6, d = n0 & 63;
                    size_t base = ((size_t)(b * HH_ + h) * TT_ + tt) * (DD_/2) + (d >> 1);
                    dst[base] = packh2(acc[im][in][0] * qs, acc[im][in][1] * qs);
                    dst[base + 8 * (DD_/2)] = packh2(acc[im][in][2] * qs, acc[im][in][3] * qs);
                }
            }
        }
    }
}

// ============================================================================
// Flash attention (causal), register-resident P, f16x2 softmax,
// row sums via ones-column mma, V via ldmatrix.x4.trans.
// Grid (8,32) = ONE uniform wave: each CTA processes q-tile pair
// {15 - bx, bx}; per-CTA k-tile count = 34, exactly balanced.
// CTA = 128 q-rows, 4 warps x 32 q-rows, 128 thr.
// K/V 64-row tiles in a 3-stage cp.async ring, single sync per tile.
// 73.7KB smem -> 2 CTAs/SM.
// ============================================================================
// bytes: sQ[128][72h] @0 (18432), sK[3][64][72h] @18432, sV[3][64][72h] @46080
#define A_K_OFF 18432u
#define A_V_OFF 46080u
#define A_STG_B 9216u
#define ATTN_SMEM_BYTES 73728

__global__ void __launch_bounds__(128, 2) attn_kernel()
{
    extern __shared__ unsigned smem[];
    const unsigned sbase = smem_u32(smem);

    const int bh = blockIdx.y;                    // b*16 + h
    const __half* Qp = (const __half*)g_Q + (size_t)bh * TT_ * DD_;
    const __half* Kp = (const __half*)g_K + (size_t)bh * TT_ * DD_;
    const __half* Vp = (const __half*)g_V + (size_t)bh * TT_ * DD_;

    const int tid = threadIdx.x;
    const int warp = tid >> 5, lane = tid & 31;
    const int g = lane >> 2, t = lane & 3;
    const int b = bh >> 4, h = bh & 15;

    // ldmatrix per-lane relative offsets
    unsigned qRel[2], kRel[4], vRel[4];
    {
        int rA = (lane & 15), kA = (lane >> 4) * 8;
        #pragma unroll
        for (int im = 0; im < 2; im++)
            qRel[im] = (unsigned)((warp * 32 + im * 16 + rA) * 72 + kA) * 2u;
        int rB = ((lane >> 4) & 1) * 8 + (lane & 7);
        int kB = ((lane >> 3) & 1) * 8;
        #pragma unroll
        for (int j = 0; j < 4; j++)
            kRel[j] = A_K_OFF + (unsigned)((j * 16 + rB) * 72 + kB) * 2u;
        int rV = lane & 15, cV = (lane >> 4) * 8;
        #pragma unroll
        for (int j = 0; j < 4; j++)
            vRel[j] = A_V_OFF + (unsigned)(rV * 72 + j * 16 + cV) * 2u;
    }

    auto load_kv = [&](int s, int kt) {
        #pragma unroll
        for (int i = 0; i < 4; i++) {
            int id = tid + (i << 7);
            int r = id >> 3, c = id & 7;
            cpa(sbase + A_K_OFF + (unsigned)s * A_STG_B + (unsigned)r * 144u + (unsigned)c * 16u,
                Kp + (size_t)(kt + r) * DD_ + c * 8);
            cpa(sbase + A_V_OFF + (unsigned)s * A_STG_B + (unsigned)r * 144u + (unsigned)c * 16u,
                Vp + (size_t)(kt + r) * DD_ + c * 8);
        }
    };

    const unsigned ones_b[2] = {0x3C003C00u, 0x3C003C00u};  // half2(1,1)

    #pragma unroll 1
    for (int pass = 0; pass < 2; ++pass) {
        if (pass) __syncthreads();            // smem reuse across passes

        const int qt = pass ? (int)blockIdx.x : 15 - (int)blockIdx.x;
        const int q0 = qt * 128;
        const int nkt = (q0 >> 6) + 2;        // k-tiles: kt = 0 .. q0+64 (>=2)
        const int wrow_min = q0 + warp * 32;

        // ---- prologue: Q (128x64) + KV stage 0, then KV stage 1 ----
        {
            #pragma unroll
            for (int i = 0; i < 8; i++) {                 // Q: 1024 chunks
                int id = tid + (i << 7);
                int r = id >> 3, c = id & 7;
                cpa(sbase + (unsigned)r * 144u + (unsigned)c * 16u,
                    Qp + (size_t)(q0 + r) * DD_ + c * 8);
            }
            load_kv(0, 0);
            CP_COMMIT();
            load_kv(1, 64);
            CP_COMMIT();
        }

        float m[2][2];
        #pragma unroll
        for (int i = 0; i < 2; i++)
            #pragma unroll
            for (int j = 0; j < 2; j++) m[i][j] = -INFINITY;

        // o[im][0..7] = output, o[im][8] = row sums (V ones column)
        float o[2][9][4];
        #pragma unroll
        for (int im = 0; im < 2; im++)
            #pragma unroll
            for (int in = 0; in < 9; in++)
                #pragma unroll
                for (int r = 0; r < 4; r++) o[im][in][r] = 0.f;

        int s = 0;
        #pragma unroll 1
        for (int it = 0; it < nkt; ++it) {
            const int kt = it * 64;
            if (it + 1 < nkt) { CP_WAIT1(); } else { CP_WAIT0(); }
            __syncthreads();
            if (it + 2 < nkt) {
                int s2 = s + 2; if (s2 >= 3) s2 -= 3;
                load_kv(s2, kt + 128);
                CP_COMMIT();
            }

            if (kt < wrow_min + 32) {
                const unsigned stgK = sbase + (unsigned)s * A_STG_B;

                // ---- S = Q K^T (pre-scaled, log2 domain) ----
                float sreg[2][8][4];
                #pragma unroll
                for (int im = 0; im < 2; im++)
                    #pragma unroll
                    for (int in = 0; in < 8; in++)
                        #pragma unroll
                        for (int r = 0; r < 4; r++) sreg[im][in][r] = 0.f;

                #pragma unroll
                for (int ks8 = 0; ks8 < 4; ks8++) {
                    const unsigned ko = (unsigned)ks8 * 32u;
                    unsigned qa[2][4], kb[8][2];
                    #pragma unroll
                    for (int im = 0; im < 2; im++)
                        ldsm4(qa[im], sbase + qRel[im] + ko);
                    #pragma unroll
                    for (int j = 0; j < 4; j++)
                        ldsm4(&kb[2*j][0], stgK + kRel[j] + ko);
                    #pragma unroll
                    for (int im = 0; im < 2; im++)
                        #pragma unroll
                        for (int in = 0; in < 8; in++)
                            mma16(sreg[im][in], qa[im], kb[in]);
                }

                // ---- causal mask + row max (fp32) ----
                const bool needmask = (kt + 63 > wrow_min);
                float mx[2][2];
                #pragma unroll
                for (int im = 0; im < 2; im++) {
                    const int rqa = wrow_min + im * 16 + g;
                    const int rqb = rqa + 8;
                    float a0 = -INFINITY, a1 = -INFINITY;
                    #pragma unroll
                    for (int in = 0; in < 8; in++) {
                        int c = kt + in * 8 + 2 * t;
                        float x0 = sreg[im][in][0];
                        float x1 = sreg[im][in][1];
                        float x2 = sreg[im][in][2];
                        float x3 = sreg[im][in][3];
                        if (needmask) {
                            if (c     > rqa) x0 = -INFINITY;
                            if (c + 1 > rqa) x1 = -INFINITY;
                            if (c     > rqb) x2 = -INFINITY;
                            if (c + 1 > rqb) x3 = -INFINITY;
                        }
                        sreg[im][in][0] = x0; sreg[im][in][1] = x1;
                        sreg[im][in][2] = x2; sreg[im][in][3] = x3;
                        a0 = fmaxf(a0, fmaxf(x0, x1));
                        a1 = fmaxf(a1, fmaxf(x2, x3));
                    }
                    a0 = fmaxf(a0, __shfl_xor_sync(0xffffffffu, a0, 1));
                    a0 = fmaxf(a0, __shfl_xor_sync(0xffffffffu, a0, 2));
                    a1 = fmaxf(a1, __shfl_xor_sync(0xffffffffu, a1, 1));
                    a1 = fmaxf(a1, __shfl_xor_sync(0xffffffffu, a1, 2));
                    mx[im][0] = a0; mx[im][1] = a1;
                }

                float cor[2][2];
                #pragma unroll
                for (int im = 0; im < 2; im++)
                    #pragma unroll
                    for (int hf = 0; hf < 2; hf++) {
                        float nm = fmaxf(m[im][hf], mx[im][hf]);
                        cor[im][hf] = ex2(m[im][hf] - nm);
                        m[im][hf] = nm;
                    }

                // ---- P = 2^(x-m) via f16x2 MUFU; pk is PV-A-fragment-ready ----
                unsigned pk[2][8][2];
                #pragma unroll
                for (int im = 0; im < 2; im++) {
                    const unsigned mh0 = packh2(m[im][0], m[im][0]);
                    const unsigned mh1 = packh2(m[im][1], m[im][1]);
                    #pragma unroll
                    for (int in = 0; in < 8; in++) {
                        unsigned xa = packh2(sreg[im][in][0], sreg[im][in][1]);
                        unsigned xb = packh2(sreg[im][in][2], sreg[im][in][3]);
                        pk[im][in][0] = ex2h2(hsub2(xa, mh0));
                        pk[im][in][1] = ex2h2(hsub2(xb, mh1));
                    }
                }

                // rescale O (incl. sum column 8)
                #pragma unroll
                for (int im = 0; im < 2; im++)
                    #pragma unroll
                    for (int in = 0; in < 9; in++) {
                        o[im][in][0] *= cor[im][0]; o[im][in][1] *= cor[im][0];
                        o[im][in][2] *= cor[im][1]; o[im][in][3] *= cor[im][1];
                    }

                // ---- O += P V  (+ row sums via ones column) ----
                const unsigned stgV = sbase + (unsigned)s * A_STG_B;
                #pragma unroll
                for (int j2 = 0; j2 < 4; j2++) {              // kv k-steps of 16
                    const unsigned kvo = (unsigned)j2 * 2304u;  // 16 kv-rows * 144B
                    unsigned vb[8][2];
                    #pragma unroll
                    for (int j = 0; j < 4; j++)
                        ldsm4t(&vb[2*j][0], stgV + vRel[j] + kvo);
                    #pragma unroll
                    for (int im = 0; im < 2; im++) {
                        unsigned a[4];
                        a[0] = pk[im][2*j2  ][0];
                        a[1] = pk[im][2*j2  ][1];
                        a[2] = pk[im][2*j2+1][0];
                        a[3] = pk[im][2*j2+1][1];
                        #pragma unroll
                        for (int in = 0; in < 8; in++)
                            mma16(o[im][in], a, vb[in]);
                        mma16(o[im][8], a, ones_b);           // row sums
                    }
                }
            }
            if (++s >= 3) s = 0;
        }

        // ---- normalize by l = o[im][8], write half2 merged-head output ----
        #pragma unroll
        for (int im = 0; im < 2; im++) {
            float inv0 = 1.f / o[im][8][0];
            float inv1 = 1.f / o[im][8][2];
            int r0 = q0 + warp * 32 + im * 16 + g;
            #pragma unroll
            for (int in = 0; in < 8; in++) {
                int cu = h * 32 + in * 4 + t;             // half2 unit col
                size_t base0 = ((size_t)(b * TT_ + r0)     * (CC_/2)) + cu;
                size_t base1 = ((size_t)(b * TT_ + r0 + 8) * (CC_/2)) + cu;
                g_Yc[base0] = packh2(o[im][in][0] * inv0, o[im][in][1] * inv0);
                g_Yc[base1] = packh2(o[im][in][2] * inv1, o[im][in][3] * inv1);
            }
        }
    }
}

// ============================================================================
// launch
// ============================================================================
extern "C" void kernel_launch(void* const* d_in, const int* in_sizes, int n_in,
                              void* d_out, int out_size)
{
    const float* X  = (const float*)d_in[0];
    const float* Wq = (const float*)d_in[1];
    const float* Wk = (const float*)d_in[2];
    const float* Wv = (const float*)d_in[3];
    const float* Wo = (const float*)d_in[4];
    float* out = (float*)d_out;

    cudaFuncSetAttribute(gemm_fp16<1>, cudaFuncAttributeMaxDynamicSharedMemorySize,
                         GEMM_SMEM_BYTES);
    cudaFuncSetAttribute(gemm_fp16<0>, cudaFuncAttributeMaxDynamicSharedMemorySize,
                         GEMM_SMEM_BYTES);
    cudaFuncSetAttribute(attn_kernel, cudaFuncAttributeMaxDynamicSharedMemorySize,
                         ATTN_SMEM_BYTES);

    unsigned *Xt = nullptr, *Wt = nullptr, *Yc = nullptr;
    cudaGetSymbolAddress((void**)&Xt, g_Xt);
    cudaGetSymbolAddress((void**)&Wt, g_Wt);
    cudaGetSymbolAddress((void**)&Yc, g_Yc);

    // 0) fp16 pre-conversion
    conv_kernel<<<8192, 256>>>((const float4*)X, (const float4*)Wq,
                               (const float4*)Wk, (const float4*)Wv,
                               (const float4*)Wo);

    // 1) QKV: grid (8,32) = 256 CTAs (one wave), 3 passes/CTA over Wq/Wk/Wv
    gemm_fp16<1><<<dim3(8, 32), 128, GEMM_SMEM_BYTES>>>(
        (const __half*)Xt, (const __half*)Wt, nullptr);

    // 2) attention: grid (8,32) = 256 CTAs (one wave), balanced q-tile pairs
    attn_kernel<<<dim3(8, 32), 128, ATTN_SMEM_BYTES>>>();

    // 3) output projection: M=4096, N=1024 (8 tiles of 128), K=1024
    gemm_fp16<0><<<dim3(8, 32), 128, GEMM_SMEM_BYTES>>>(
        (const __half*)Yc, (const __half*)Wt + 3*1024*1024, out);
}

// round 14
// speedup vs baseline: 1.6373x; 1.0210x over previous
#include <cuda_runtime.h>
#include <cuda_fp16.h>
#include <cstdint>
#include <cstdio>

// ---------------- problem constants ----------------
#define BB_ 2
#define TT_ 2048
#define CC_ 1024
#define HH_ 16
#define DD_ 64

// exp(s/8) = 2^(s * log2(e)/8); folded into Q at the QKV epilogue
#define SOFTMAX_SCL 0.18033688011112042f

// ---------------- scratch: fp16 stored as unsigned (half2 units) ----------------
__device__ __align__(16) unsigned g_Xt[BB_*TT_*CC_/2];      // X fp16 [m][k]
__device__ __align__(16) unsigned g_Wt[4*CC_*CC_/2];        // Wq|Wk|Wv|Wo fp16 [n][k]
__device__ __align__(16) unsigned g_Q [BB_*HH_*TT_*DD_/2];  // [b,h,t,d]  (pre-scaled)
__device__ __align__(16) unsigned g_K [BB_*HH_*TT_*DD_/2];  // [b,h,t,d]
__device__ __align__(16) unsigned g_V [BB_*HH_*TT_*DD_/2];  // [b,h,t,d]
__device__ __align__(16) unsigned g_Yc[BB_*TT_*CC_/2];      // merged heads [b,t,c]

// ---------------- helpers ----------------
__device__ __forceinline__ float ex2(float x) {
    float y;
    asm("ex2.approx.f32 %0, %1;" : "=f"(y) : "f"(x));
    return y;
}
__device__ __forceinline__ unsigned ex2h2(unsigned x) {
    unsigned y;
    asm("ex2.approx.f16x2 %0, %1;" : "=r"(y) : "r"(x));
    return y;
}
__device__ __forceinline__ unsigned hsub2(unsigned a, unsigned b) {
    unsigned y;
    asm("sub.f16x2 %0, %1, %2;" : "=r"(y) : "r"(a), "r"(b));
    return y;
}
__device__ __forceinline__ unsigned packh2(float a, float b) {
    __half2 h = __floats2half2_rn(a, b);
    return *(unsigned*)&h;
}
__device__ __forceinline__ void mma16(float* d, const unsigned* a, const unsigned* b) {
    asm volatile(
        "mma.sync.aligned.m16n8k16.row.col.f32.f16.f16.f32 "
        "{%0,%1,%2,%3},{%4,%5,%6,%7},{%8,%9},{%0,%1,%2,%3};"
        : "+f"(d[0]), "+f"(d[1]), "+f"(d[2]), "+f"(d[3])
        : "r"(a[0]), "r"(a[1]), "r"(a[2]), "r"(a[3]),
          "r"(b[0]), "r"(b[1]));
}
__device__ __forceinline__ void ldsm4(unsigned* r, unsigned addr) {
    asm volatile("ldmatrix.sync.aligned.m8n8.x4.shared.b16 {%0,%1,%2,%3}, [%4];"
        : "=r"(r[0]), "=r"(r[1]), "=r"(r[2]), "=r"(r[3]) : "r"(addr));
}
__device__ __forceinline__ void ldsm4t(unsigned* r, unsigned addr) {
    asm volatile("ldmatrix.sync.aligned.m8n8.x4.trans.shared.b16 {%0,%1,%2,%3}, [%4];"
        : "=r"(r[0]), "=r"(r[1]), "=r"(r[2]), "=r"(r[3]) : "r"(addr));
}
__device__ __forceinline__ void cpa(unsigned dst, const void* src) {
    asm volatile("cp.async.cg.shared.global [%0], [%1], 16;" :: "r"(dst), "l"(src));
}
#define CP_COMMIT() asm volatile("cp.async.commit_group;")
#define CP_WAIT1()  asm volatile("cp.async.wait_group 1;")
#define CP_WAIT0()  asm volatile("cp.async.wait_group 0;")
__device__ __forceinline__ unsigned smem_u32(const void* p) {
    return (unsigned)__cvta_generic_to_shared(p);
}

// ============================================================================
// one-shot fp16 conversion: X (1M float4) + 4 weights (256K float4 each)
// ============================================================================
__global__ void __launch_bounds__(256) conv_kernel(
    const float4* __restrict__ X,  const float4* __restrict__ Wq,
    const float4* __restrict__ Wk, const float4* __restrict__ Wv,
    const float4* __restrict__ Wo)
{
    int i = blockIdx.x * 256 + threadIdx.x;          // 0 .. 2M-1
    const float4* src;
    uint2* dst;
    if (i < (1 << 20)) {
        src = X + i;
        dst = (uint2*)g_Xt + i;
    } else {
        int j = i - (1 << 20);
        int w = j >> 18, r = j & 0x3FFFF;
        const float4* s4 = (w == 0) ? Wq : (w == 1) ? Wk : (w == 2) ? Wv : Wo;
        src = s4 + r;
        dst = (uint2*)g_Wt + (w << 18) + r;
    }
    float4 v = *src;
    *dst = make_uint2(packh2(v.x, v.y), packh2(v.z, v.w));
}

// ============================================================================
// fp16 GEMM: C[m,n] = sum_k A[m,k]*B[n,k]  (NT), K=1024.
// CTA 128x128, 4 warps (2m x 2n), warp tile 64x64, m16n8k16 + ldmatrix.x4.
// CONTINUOUS 3-stage cp.async ring across all passes (no drain between
// passes); acc reset / epilogue inline at chunk boundaries i%16==0 / ==15.
// 128 thr; 110.6KB smem -> 2 CTAs/SM.
// MODE 1: grid (8,32), 3 passes (Wq/Wk/Wv) = 48 chunks; scatters Q/K/V.
// MODE 0: 1 pass (Wo), A=g_Yc, writes fp32 Cout.
// ============================================================================
#define G_ROW_B 144u
#define G_A_B   18432u          // A block bytes (128*144)
#define G_STG_B 36864u          // A+B per stage
#define GEMM_SMEM_BYTES (3*36864)

template<int MODE>
__global__ void __launch_bounds__(128, 2) gemm_fp16(
    const __half* __restrict__ A,
    const __half* __restrict__ B,
    float* __restrict__ Cout)
{
    extern __shared__ unsigned smem[];
    const unsigned sbase = smem_u32(smem);

    const int tid  = threadIdx.x;
    const int bm   = blockIdx.y * 128;
    const int bn   = blockIdx.x * 128;        // 0..896 (N region = 1024)
    const int warp = tid >> 5, lane = tid & 31;
    const int g = lane >> 2, t = lane & 3;
    const int wm = (warp & 1) * 64;           // warp m offset
    const int wn = (warp >> 1) * 64;          // warp n offset

    const __half* Ap = A + (size_t)bm * 1024;

    // ldmatrix per-lane relative byte offsets
    unsigned aRel[4], bRel[4];
    {
        int rA = (lane & 15), kA = (lane >> 4) * 8;
        #pragma unroll
        for (int im = 0; im < 4; im++)
            aRel[im] = (unsigned)((wm + im * 16 + rA) * 72 + kA) * 2u;
        int rB = ((lane >> 4) & 1) * 8 + (lane & 7);
        int kB = ((lane >> 3) & 1) * 8;
        #pragma unroll
        for (int j = 0; j < 4; j++)
            bRel[j] = G_A_B + (unsigned)((wn + j * 16 + rB) * 72 + kB) * 2u;
    }

    // chunk c (global): pass = c>>4, k0 = (c&15)*64
    auto load_chunk = [&](int s, int c) {
        const unsigned st = sbase + (unsigned)s * G_STG_B;
        const int k0 = (c & 15) * 64;
        const __half* Bp = B + ((size_t)(c >> 4) << 20) + (size_t)bn * 1024;
        #pragma unroll
        for (int i = 0; i < 8; i++) {                   // A: 1024 chunks
            int id = tid + (i << 7);
            int r = id >> 3, cc = id & 7;
            cpa(st + (unsigned)r * G_ROW_B + (unsigned)cc * 16u,
                Ap + (size_t)r * 1024 + k0 + cc * 8);
        }
        #pragma unroll
        for (int i = 0; i < 8; i++) {                   // B: 1024 chunks
            int id = tid + (i << 7);
            int r = id >> 3, cc = id & 7;
            cpa(st + G_A_B + (unsigned)r * G_ROW_B + (unsigned)cc * 16u,
                Bp + (size_t)r * 1024 + k0 + cc * 8);
        }
    };

    load_chunk(0, 0);
    CP_COMMIT();
    load_chunk(1, 1);
    CP_COMMIT();

    const int NIT = (MODE == 1) ? 48 : 16;
    float acc[4][8][4];

    int s = 0;
    #pragma unroll 1
    for (int i = 0; i < NIT; ++i) {
        if (i + 1 < NIT) { CP_WAIT1(); } else { CP_WAIT0(); }
        __syncthreads();
        if (i + 2 < NIT) {
            int s2 = s + 2; if (s2 >= 3) s2 -= 3;
            load_chunk(s2, i + 2);
            CP_COMMIT();
        }

        if ((i & 15) == 0) {
            #pragma unroll
            for (int a = 0; a < 4; a++)
                #pragma unroll
                for (int b2 = 0; b2 < 8; b2++)
                    #pragma unroll
                    for (int r = 0; r < 4; r++) acc[a][b2][r] = 0.f;
        }

        const unsigned stg = sbase + (unsigned)s * G_STG_B;
        #pragma unroll
        for (int ks8 = 0; ks8 < 4; ks8++) {             // 4 k-steps of 16
            const unsigned ko = (unsigned)ks8 * 32u;    // 16 halves = 32B
            unsigned afr[4][4], bfr[8][2];
            #pragma unroll
            for (int im = 0; im < 4; im++)
                ldsm4(afr[im], stg + aRel[im] + ko);
            #pragma unroll
            for (int j = 0; j < 4; j++)
                ldsm4(&bfr[2*j][0], stg + bRel[j] + ko);
            #pragma unroll
            for (int im = 0; im < 4; im++)
                #pragma unroll
                for (int in = 0; in < 8; in++)
                    mma16(acc[im][in], afr[im], bfr[in]);
        }

        // ---------------- inline epilogue at pass end ----------------
        if ((i & 15) == 15) {
            if (MODE == 0) {
                #pragma unroll
                for (int im = 0; im < 4; im++) {
                    #pragma unroll
                    for (int in = 0; in < 8; in++) {
                        int r0 = bm + wm + im * 16 + g;
                        int c0 = bn + wn + in * 8 + 2 * t;
                        *(float2*)(Cout + (size_t)r0 * 1024 + c0) =
                            make_float2(acc[im][in][0], acc[im][in][1]);
                        *(float2*)(Cout + (size_t)(r0 + 8) * 1024 + c0) =
                            make_float2(acc[im][in][2], acc[im][in][3]);
                    }
                }
            } else {
                const int pass = i >> 4;
                const float qs = (pass == 0) ? SOFTMAX_SCL : 1.f;
                unsigned* dst = (pass == 0) ? g_Q : (pass == 1) ? g_K : g_V;
                #pragma unroll
                for (int im = 0; im < 4; im++) {
                    #pragma unroll
                    for (int in = 0; in < 8; in++) {
                        int r0 = bm + wm + im * 16 + g;      // m = b*2048 + t
                        int b  = r0 >> 11, tt = r0 & 2047;
                        int n0 = bn + wn + in * 8 + 2 * t;
                        int h  = n0 >> 6, d = n0 & 63;
                        size_t base = ((size_t)(b * HH_ + h) * TT_ + tt) * (DD_/2) + (d >> 1);
                        dst[base] = packh2(acc[im][in][0] * qs, acc[im][in][1] * qs);
                        dst[base + 8 * (DD_/2)] = packh2(acc[im][in][2] * qs, acc[im][in][3] * qs);
                    }
                }
            }
        }
        if (++s >= 3) s = 0;
    }
}

// ============================================================================
// Flash attention (causal), register-resident P, f16x2 softmax,
// row sums via ones-column mma, V via ldmatrix.x4.trans.
// Grid (8,32) = one uniform wave; CTA processes q-tiles {15-bx, bx} in a
// SINGLE flat k-tile schedule (34 tiles) over one CONTINUOUS 3-stage
// cp.async ring (K/V pointers identical across passes -> no drain).
// Q double-buffered; pass-1 Q prefetched 2 tiles early in the same group.
// CTA = 128 q-rows, 4 warps x 32 q-rows, 128 thr; 90KB smem -> 2 CTAs/SM.
// ============================================================================
// bytes: sQ[2][128][72h] @0 (2x18432), sK[3][64][72h] @36864,
//        sV[3][64][72h] @64512
#define A_Q_STR 18432u
#define A_K_OFF 36864u
#define A_V_OFF 64512u
#define A_STG_B 9216u
#define ATTN_SMEM_BYTES 92160

__global__ void __launch_bounds__(128, 2) attn_kernel()
{
    extern __shared__ unsigned smem[];
    const unsigned sbase = smem_u32(smem);

    const int bh = blockIdx.y;                    // b*16 + h
    const __half* Qp = (const __half*)g_Q + (size_t)bh * TT_ * DD_;
    const __half* Kp = (const __half*)g_K + (size_t)bh * TT_ * DD_;
    const __half* Vp = (const __half*)g_V + (size_t)bh * TT_ * DD_;

    const int tid = threadIdx.x;
    const int warp = tid >> 5, lane = tid & 31;
    const int g = lane >> 2, t = lane & 3;
    const int b = bh >> 4, h = bh & 15;

    const int qt0 = 15 - (int)blockIdx.x;
    const int qt1 = (int)blockIdx.x;
    const int q0a = qt0 * 128, q0b = qt1 * 128;
    const int nkt0 = 2 * qt0 + 2;                 // >= 18
    const int ntot = nkt0 + 2 * qt1 + 2;          // 34

    // ldmatrix per-lane relative offsets
    unsigned qRel[2], kRel[4], vRel[4];
    {
        int rA = (lane & 15), kA = (lane >> 4) * 8;
        #pragma unroll
        for (int im = 0; im < 2; im++)
            qRel[im] = (unsigned)((warp * 32 + im * 16 + rA) * 72 + kA) * 2u;
        int rB = ((lane >> 4) & 1) * 8 + (lane & 7);
        int kB = ((lane >> 3) & 1) * 8;
        #pragma unroll
        for (int j = 0; j < 4; j++)
            kRel[j] = A_K_OFF + (unsigned)((j * 16 + rB) * 72 + kB) * 2u;
        int rV = lane & 15, cV = (lane >> 4) * 8;
        #pragma unroll
        for (int j = 0; j < 4; j++)
            vRel[j] = A_V_OFF + (unsigned)(rV * 72 + j * 16 + cV) * 2u;
    }

    auto load_q = [&](int buf, int q0) {
        #pragma unroll
        for (int i = 0; i < 8; i++) {                 // 1024 chunks
            int id = tid + (i << 7);
            int r = id >> 3, c = id & 7;
            cpa(sbase + (unsigned)buf * A_Q_STR + (unsigned)r * 144u + (unsigned)c * 16u,
                Qp + (size_t)(q0 + r) * DD_ + c * 8);
        }
    };
    auto load_kv = [&](int s, int kt) {
        #pragma unroll
        for (int i = 0; i < 4; i++) {
            int id = tid + (i << 7);
            int r = id >> 3, c = id & 7;
            cpa(sbase + A_K_OFF + (unsigned)s * A_STG_B + (unsigned)r * 144u + (unsigned)c * 16u,
                Kp + (size_t)(kt + r) * DD_ + c * 8);
            cpa(sbase + A_V_OFF + (unsigned)s * A_STG_B + (unsigned)r * 144u + (unsigned)c * 16u,
                Vp + (size_t)(kt + r) * DD_ + c * 8);
        }
    };
    // kt for flat tile index f
    auto kt_of = [&](int f) { return (f < nkt0 ? f : f - nkt0) * 64; };

    // ---- prologue: Q0 + KV tile 0 (one group), then KV tile 1 ----
    load_q(0, q0a);
    load_kv(0, 0);
    CP_COMMIT();
    load_kv(1, kt_of(1));
    CP_COMMIT();

    const unsigned ones_b[2] = {0x3C003C00u, 0x3C003C00u};  // half2(1,1)

    float m[2][2];
    float o[2][9][4];
    #pragma unroll
    for (int i = 0; i < 2; i++)
        #pragma unroll
        for (int j = 0; j < 2; j++) m[i][j] = -INFINITY;
    #pragma unroll
    for (int im = 0; im < 2; im++)
        #pragma unroll
        for (int in = 0; in < 9; in++)
            #pragma unroll
            for (int r = 0; r < 4; r++) o[im][in][r] = 0.f;

    int s = 0;
    #pragma unroll 1
    for (int f = 0; f < ntot; ++f) {
        if (f + 1 < ntot) { CP_WAIT1(); } else { CP_WAIT0(); }
        __syncthreads();
        if (f + 2 < ntot) {
            int s2 = s + 2; if (s2 >= 3) s2 -= 3;
            load_kv(s2, kt_of(f + 2));
            if (f + 2 == nkt0) load_q(1, q0b);    // pass-1 Q rides this group
            CP_COMMIT();
        }

        const int pass = (f >= nkt0);
        if (f == nkt0) {                          // reset state for pass 1
            #pragma unroll
            for (int i2 = 0; i2 < 2; i2++)
                #pragma unroll
                for (int j2 = 0; j2 < 2; j2++) m[i2][j2] = -INFINITY;
            #pragma unroll
            for (int im = 0; im < 2; im++)
                #pragma unroll
                for (int in = 0; in < 9; in++)
                    #pragma unroll
                    for (int r = 0; r < 4; r++) o[im][in][r] = 0.f;
        }

        const int q0 = pass ? q0b : q0a;
        const int kt = kt_of(f);
        const int wrow_min = q0 + warp * 32;
        const unsigned qbase = sbase + (unsigned)pass * A_Q_STR;

        if (kt < wrow_min + 32) {
            const unsigned stgK = sbase + (unsigned)s * A_STG_B;

            // ---- S = Q K^T (pre-scaled, log2 domain) ----
            float sreg[2][8][4];
            #pragma unroll
            for (int im = 0; im < 2; im++)
                #pragma unroll
                for (int in = 0; in < 8; in++)
                    #pragma unroll
                    for (int r = 0; r < 4; r++) sreg[im][in][r] = 0.f;

            #pragma unroll
            for (int ks8 = 0; ks8 < 4; ks8++) {
                const unsigned ko = (unsigned)ks8 * 32u;
                unsigned qa[2][4], kb[8][2];
                #pragma unroll
                for (int im = 0; im < 2; im++)
                    ldsm4(qa[im], qbase + qRel[im] + ko);
                #pragma unroll
                for (int j = 0; j < 4; j++)
                    ldsm4(&kb[2*j][0], stgK + kRel[j] + ko);
                #pragma unroll
                for (int im = 0; im < 2; im++)
                    #pragma unroll
                    for (int in = 0; in < 8; in++)
                        mma16(sreg[im][in], qa[im], kb[in]);
            }

            // ---- causal mask + row max (fp32) ----
            const bool needmask = (kt + 63 > wrow_min);
            float mx[2][2];
            #pragma unroll
            for (int im = 0; im < 2; im++) {
                const int rqa = wrow_min + im * 16 + g;
                const int rqb = rqa + 8;
                float a0 = -INFINITY, a1 = -INFINITY;
                #pragma unroll
                for (int in = 0; in < 8; in++) {
                    int c = kt + in * 8 + 2 * t;
                    float x0 = sreg[im][in][0];
                    float x1 = sreg[im][in][1];
                    float x2 = sreg[im][in][2];
                    float x3 = sreg[im][in][3];
                    if (needmask) {
                        if (c     > rqa) x0 = -INFINITY;
                        if (c + 1 > rqa) x1 = -INFINITY;
                        if (c     > rqb) x2 = -INFINITY;
                        if (c + 1 > rqb) x3 = -INFINITY;
                    }
                    sreg[im][in][0] = x0; sreg[im][in][1] = x1;
                    sreg[im][in][2] = x2; sreg[im][in][3] = x3;
                    a0 = fmaxf(a0, fmaxf(x0, x1));
                    a1 = fmaxf(a1, fmaxf(x2, x3));
                }
                a0 = fmaxf(a0, __shfl_xor_sync(0xffffffffu, a0, 1));
                a0 = fmaxf(a0, __shfl_xor_sync(0xffffffffu, a0, 2));
                a1 = fmaxf(a1, __shfl_xor_sync(0xffffffffu, a1, 1));
                a1 = fmaxf(a1, __shfl_xor_sync(0xffffffffu, a1, 2));
                mx[im][0] = a0; mx[im][1] = a1;
            }

            float cor[2][2];
            #pragma unroll
            for (int im = 0; im < 2; im++)
                #pragma unroll
                for (int hf = 0; hf < 2; hf++) {
                    float nm = fmaxf(m[im][hf], mx[im][hf]);
                    cor[im][hf] = ex2(m[im][hf] - nm);
                    m[im][hf] = nm;
                }

            // ---- P = 2^(x-m) via f16x2 MUFU; pk is PV-A-fragment-ready ----
            unsigned pk[2][8][2];
            #pragma unroll
            for (int im = 0; im < 2; im++) {
                const unsigned mh0 = packh2(m[im][0], m[im][0]);
                const unsigned mh1 = packh2(m[im][1], m[im][1]);
                #pragma unroll
                for (int in = 0; in < 8; in++) {
                    unsigned xa = packh2(sreg[im][in][0], sreg[im][in][1]);
                    unsigned xb = packh2(sreg[im][in][2], sreg[im][in][3]);
                    pk[im][in][0] = ex2h2(hsub2(xa, mh0));
                    pk[im][in][1] = ex2h2(hsub2(xb, mh1));
                }
            }

            // rescale O (incl. sum column 8)
            #pragma unroll
            for (int im = 0; im < 2; im++)
                #pragma unroll
                for (int in = 0; in < 9; in++) {
                    o[im][in][0] *= cor[im][0]; o[im][in][1] *= cor[im][0];
                    o[im][in][2] *= cor[im][1]; o[im][in][3] *= cor[im][1];
                }

            // ---- O += P V  (+ row sums via ones column) ----
            const unsigned stgV = sbase + (unsigned)s * A_STG_B;
            #pragma unroll
            for (int j2 = 0; j2 < 4; j2++) {              // kv k-steps of 16
                const unsigned kvo = (unsigned)j2 * 2304u;  // 16 kv-rows * 144B
                unsigned vb[8][2];
                #pragma unroll
                for (int j = 0; j < 4; j++)
                    ldsm4t(&vb[2*j][0], stgV + vRel[j] + kvo);
                #pragma unroll
                for (int im = 0; im < 2; im++) {
                    unsigned a[4];
                    a[0] = pk[im][2*j2  ][0];
                    a[1] = pk[im][2*j2  ][1];
                    a[2] = pk[im][2*j2+1][0];
                    a[3] = pk[im][2*j2+1][1];
                    #pragma unroll
                    for (int in = 0; in < 8; in++)
                        mma16(o[im][in], a, vb[in]);
                    mma16(o[im][8], a, ones_b);           // row sums
                }
            }
        }

        // ---- inline per-pass epilogue ----
        if (f == nkt0 - 1 || f == ntot - 1) {
            #pragma unroll
            for (int im = 0; im < 2; im++) {
                float inv0 = 1.f / o[im][8][0];
                float inv1 = 1.f / o[im][8][2];
                int r0 = q0 + warp * 32 + im * 16 + g;
                #pragma unroll
                for (int in = 0; in < 8; in++) {
                    int cu = h * 32 + in * 4 + t;         // half2 unit col
                    size_t base0 = ((size_t)(b * TT_ + r0)     * (CC_/2)) + cu;
                    size_t base1 = ((size_t)(b * TT_ + r0 + 8) * (CC_/2)) + cu;
                    g_Yc[base0] = packh2(o[im][in][0] * inv0, o[im][in][1] * inv0);
                    g_Yc[base1] = packh2(o[im][in][2] * inv1, o[im][in][3] * inv1);
                }
            }
        }
        if (++s >= 3) s = 0;
    }
}

// ============================================================================
// launch
// ============================================================================
extern "C" void kernel_launch(void* const* d_in, const int* in_sizes, int n_in,
                              void* d_out, int out_size)
{
    const float* X  = (const float*)d_in[0];
    const float* Wq = (const float*)d_in[1];
    const float* Wk = (const float*)d_in[2];
    const float* Wv = (const float*)d_in[3];
    const float* Wo = (const float*)d_in[4];
    float* out = (float*)d_out;

    cudaFuncSetAttribute(gemm_fp16<1>, cudaFuncAttributeMaxDynamicSharedMemorySize,
                         GEMM_SMEM_BYTES);
    cudaFuncSetAttribute(gemm_fp16<0>, cudaFuncAttributeMaxDynamicSharedMemorySize,
                         GEMM_SMEM_BYTES);
    cudaFuncSetAttribute(attn_kernel, cudaFuncAttributeMaxDynamicSharedMemorySize,
                         ATTN_SMEM_BYTES);

    unsigned *Xt = nullptr, *Wt = nullptr, *Yc = nullptr;
    cudaGetSymbolAddress((void**)&Xt, g_Xt);
    cudaGetSymbolAddress((void**)&Wt, g_Wt);
    cudaGetSymbolAddress((void**)&Yc, g_Yc);

    // 0) fp16 pre-conversion
    conv_kernel<<<8192, 256>>>((const float4*)X, (const float4*)Wq,
                               (const float4*)Wk, (const float4*)Wv,
                               (const float4*)Wo);

    // 1) QKV: grid (8,32) = 256 CTAs (one wave), continuous 48-chunk ring
    gemm_fp16<1><<<dim3(8, 32), 128, GEMM_SMEM_BYTES>>>(
        (const __half*)Xt, (const __half*)Wt, nullptr);

    // 2) attention: grid (8,32) = 256 CTAs (one wave), continuous 34-tile ring
    attn_kernel<<<dim3(8, 32), 128, ATTN_SMEM_BYTES>>>();

    // 3) output projection: M=4096, N=1024 (8 tiles of 128), K=1024
    gemm_fp16<0><<<dim3(8, 32), 128, GEMM_SMEM_BYTES>>>(
        (const __half*)Yc, (const __half*)Wt + 3*1024*1024, out);
}